// round 15
// baseline (speedup 1.0000x reference)
#include <cuda_runtime.h>
#include <math.h>

// SymmetricChannel, fused single-kernel — FINAL (converged; 6 replicates:
// dur 61.31-61.63us, mean 61.44, sigma 0.11; kernel 54.1-55.6us, DRAM 80-83%).
// 402 MB compulsory traffic @ ~6.5 TB/s ≈ 93% of measured GB300 HBM ceiling.
//
// Config search summary (R2-R14), all cells measured, all regressions explained:
//   width:       4 > 8 (8-wide -> 32B noise lane stride -> 1 sector/lane ->
//                2x L1 wavefronts; L1 82-87% binding in both R3 and R11)
//   cache:       __ldcs msg (read-once) WIN; __ldcs noise LOSS; __stcs out OK
//   persistence: 1-wave persistent grid LOSS on graph replay (R5)
//   block size:  256 ~ 128 > 512
//   fusion:      entropy fused into main kernel WIN (-2us, single launch)
//   noise vec:   impossible (255-float rows, bases at 1020*r bytes, unaligned)
//   shfl redistribution of noise: rejected — trades non-binding L1 (49%) for
//                issue-pipe pressure (16 SHFL/thread, lat 26).
//
// out[b,l,k] = messages[b,l,k] unless mapped noise column < P:
//   k in [0,253]: zero iff noise[b,l,k+1] < P
//   k == 254   : never zeroed
//   k == 255   : zero iff noise[b,l,0]   < P
// Entropy: sym_ent = entropy + C, ent_copy = entropy, per-b (L=32) warp sums.

#define P_ERR 0.1f

__global__ void __launch_bounds__(256)
chan_fused_kernel(const float* __restrict__ msg,
                  const float* __restrict__ noise,
                  const float* __restrict__ ent,
                  float* __restrict__ out,
                  float* __restrict__ sym_sum,
                  float* __restrict__ sym_ent,
                  float* __restrict__ ent_sum,
                  float* __restrict__ ent_copy,
                  float cst, long n4, long BL) {
    long i = (long)blockIdx.x * blockDim.x + threadIdx.x;
    if (i >= n4) return;

    // messages: read-once, no reuse anywhere -> evict-first load.
    float4 m = __ldcs(reinterpret_cast<const float4*>(msg) + i);

    // 64 float4 per 256-wide row
    long row = i >> 6;
    int k0 = ((int)i & 63) << 2;
    const float* __restrict__ nrow = noise + row * 255;

    float v[4] = {m.x, m.y, m.z, m.w};
#pragma unroll
    for (int c = 0; c < 4; ++c) {
        int k = k0 + c;
        if (k != 254) {
            int nidx = (k == 255) ? 0 : (k + 1);
            // noise: default caching — 16B lane stride gives 2 lanes/sector reuse.
            if (__ldg(nrow + nidx) < P_ERR) v[c] = 0.0f;
        }
    }

    // Output never re-read: evict-first store.
    __stcs(reinterpret_cast<float4*>(out) + i, make_float4(v[0], v[1], v[2], v[3]));

    // ---- fused entropy path: first B*L threads (warp == one batch row) ----
    if (i < BL) {
        int lane = (int)i & 31;
        float e = __ldg(ent + i);
        sym_ent[i]  = e + cst;
        ent_copy[i] = e;

        float s = e;
#pragma unroll
        for (int o = 16; o > 0; o >>= 1)
            s += __shfl_xor_sync(0xFFFFFFFFu, s, o);

        if (lane == 0) {
            long b = i >> 5;
            ent_sum[b] = s;
            sym_sum[b] = s + 32.0f * cst;
        }
    }
}

extern "C" void kernel_launch(void* const* d_in, const int* in_sizes, int n_in,
                              void* d_out, int out_size) {
    const float* messages = (const float*)d_in[0];
    const float* entropy  = (const float*)d_in[1];
    const float* noise    = (const float*)d_in[2];

    const long N  = in_sizes[0];          // B*L*V = 33,554,432
    const long BL = in_sizes[1];          // B*L   = 131,072
    const int  L  = 32;
    const int  B  = (int)(BL / L);        // 4096

    float* out      = (float*)d_out;                 // [B,L,V]
    float* sym_sum  = out + N;                       // [B]
    float* sym_ent  = sym_sum + B;                   // [B,L]
    float* ent_sum  = sym_ent + BL;                  // [B]
    float* ent_copy = ent_sum + B;                   // [B,L]

    // const = Hb(p) + log2(V-2)
    const double p = 0.1, q = 0.9;
    const double hb = -(p * log2(p) + q * log2(q));
    const float cst = (float)(hb + log2(254.0));

    const long n4 = N / 4;                // 8,388,608 float4 elements
    const int threads = 256;
    const int blocks = (int)((n4 + threads - 1) / threads);   // 32768
    chan_fused_kernel<<<blocks, threads>>>(messages, noise, entropy, out,
                                           sym_sum, sym_ent, ent_sum, ent_copy,
                                           cst, n4, BL);
}

// round 16
// speedup vs baseline: 1.0105x; 1.0105x over previous
#include <cuda_runtime.h>
#include <math.h>

// SymmetricChannel, fused single-kernel.
// Probe: the one unmeasured config cell — 4-wide + __ldcs on noise.
// Rationale: noise is temporally read-once (sector sharing happens within
// the LDG wavefront / adjacent unrolled loads, inside the evict window);
// retained noise lines are dead. Full-streaming (ldcs msg+noise, stcs out)
// frees all of L2 for the inbound stream. R3/R11 proved 8-wide was the
// regression cause, not the noise cache policy — this isolates it at 4-wide.
//
// out[b,l,k] = messages[b,l,k] unless mapped noise column < P:
//   k in [0,253]: zero iff noise[b,l,k+1] < P
//   k == 254   : never zeroed
//   k == 255   : zero iff noise[b,l,0]   < P
// Entropy: sym_ent = entropy + C, ent_copy = entropy, per-b (L=32) warp sums.

#define P_ERR 0.1f

__global__ void __launch_bounds__(256)
chan_fused_kernel(const float* __restrict__ msg,
                  const float* __restrict__ noise,
                  const float* __restrict__ ent,
                  float* __restrict__ out,
                  float* __restrict__ sym_sum,
                  float* __restrict__ sym_ent,
                  float* __restrict__ ent_sum,
                  float* __restrict__ ent_copy,
                  float cst, long n4, long BL) {
    long i = (long)blockIdx.x * blockDim.x + threadIdx.x;
    if (i >= n4) return;

    // messages: read-once -> evict-first load.
    float4 m = __ldcs(reinterpret_cast<const float4*>(msg) + i);

    // 64 float4 per 256-wide row
    long row = i >> 6;
    int k0 = ((int)i & 63) << 2;
    const float* __restrict__ nrow = noise + row * 255;

    float v[4] = {m.x, m.y, m.z, m.w};
#pragma unroll
    for (int c = 0; c < 4; ++c) {
        int k = k0 + c;
        if (k != 254) {
            int nidx = (k == 255) ? 0 : (k + 1);
            // noise: also temporally read-once -> evict-first (probe).
            if (__ldcs(nrow + nidx) < P_ERR) v[c] = 0.0f;
        }
    }

    // Output never re-read: evict-first store.
    __stcs(reinterpret_cast<float4*>(out) + i, make_float4(v[0], v[1], v[2], v[3]));

    // ---- fused entropy path: first B*L threads (warp == one batch row) ----
    if (i < BL) {
        int lane = (int)i & 31;
        float e = __ldg(ent + i);
        sym_ent[i]  = e + cst;
        ent_copy[i] = e;

        float s = e;
#pragma unroll
        for (int o = 16; o > 0; o >>= 1)
            s += __shfl_xor_sync(0xFFFFFFFFu, s, o);

        if (lane == 0) {
            long b = i >> 5;
            ent_sum[b] = s;
            sym_sum[b] = s + 32.0f * cst;
        }
    }
}

extern "C" void kernel_launch(void* const* d_in, const int* in_sizes, int n_in,
                              void* d_out, int out_size) {
    const float* messages = (const float*)d_in[0];
    const float* entropy  = (const float*)d_in[1];
    const float* noise    = (const float*)d_in[2];

    const long N  = in_sizes[0];          // B*L*V = 33,554,432
    const long BL = in_sizes[1];          // B*L   = 131,072
    const int  L  = 32;
    const int  B  = (int)(BL / L);        // 4096

    float* out      = (float*)d_out;                 // [B,L,V]
    float* sym_sum  = out + N;                       // [B]
    float* sym_ent  = sym_sum + B;                   // [B,L]
    float* ent_sum  = sym_ent + BL;                  // [B]
    float* ent_copy = ent_sum + B;                   // [B,L]

    // const = Hb(p) + log2(V-2)
    const double p = 0.1, q = 0.9;
    const double hb = -(p * log2(p) + q * log2(q));
    const float cst = (float)(hb + log2(254.0));

    const long n4 = N / 4;                // 8,388,608 float4 elements
    const int threads = 256;
    const int blocks = (int)((n4 + threads - 1) / threads);   // 32768
    chan_fused_kernel<<<blocks, threads>>>(messages, noise, entropy, out,
                                           sym_sum, sym_ent, ent_sum, ent_copy,
                                           cst, n4, BL);
}